// round 1
// baseline (speedup 1.0000x reference)
#include <cuda_runtime.h>
#include <math.h>
#include <stdint.h>

// Problem constants
#define B_ 32
#define N_ 196
#define C_ 768
#define H_ 12
#define L_ 4
#define DFF_ 3072
#define ROWS_ (B_*N_)          // 6272
#define HD_ 64                 // C_/H_

// ---------------- scratch (device globals; no runtime allocation) ----------
__device__ float g_ln[ROWS_*C_];          // LN output
__device__ float g_qkv[ROWS_*3*C_];       // qkv projection
__device__ float g_attn[ROWS_*C_];        // attention output (head-concat)
__device__ float g_hidden[ROWS_*DFF_];    // MLP hidden
__device__ float g_fused[B_*L_*C_];       // latent bottleneck output

// ---------------------------------------------------------------------------
// LayerNorm: one block (256 thr) per row, C=768 => 3 elems/thread
// ---------------------------------------------------------------------------
__global__ void ln_kernel(const float* __restrict__ in,
                          const float* __restrict__ gam,
                          const float* __restrict__ bet,
                          float* __restrict__ out) {
    __shared__ float red[256];
    int row = blockIdx.x, t = threadIdx.x;
    const float* r = in + (size_t)row * C_;
    float v0 = r[t], v1 = r[t + 256], v2 = r[t + 512];
    red[t] = v0 + v1 + v2;
    __syncthreads();
    #pragma unroll
    for (int o = 128; o > 0; o >>= 1) {
        if (t < o) red[t] += red[t + o];
        __syncthreads();
    }
    float mean = red[0] * (1.f / C_);
    __syncthreads();
    float d0 = v0 - mean, d1 = v1 - mean, d2 = v2 - mean;
    red[t] = d0 * d0 + d1 * d1 + d2 * d2;
    __syncthreads();
    #pragma unroll
    for (int o = 128; o > 0; o >>= 1) {
        if (t < o) red[t] += red[t + o];
        __syncthreads();
    }
    float inv = rsqrtf(red[0] * (1.f / C_) + 1e-6f);
    float* o = out + (size_t)row * C_;
    o[t]       = d0 * inv * gam[t]       + bet[t];
    o[t + 256] = d1 * inv * gam[t + 256] + bet[t + 256];
    o[t + 512] = d2 * inv * gam[t + 512] + bet[t + 512];
}

// ---------------------------------------------------------------------------
// Tiled SGEMM: C[M,N] = A[M,K] @ B[K,N] (+bias) (+gelu | +residual)
// BM=BN=128, BK=8, 256 threads, 8x8 microtile. All dims divide tiles exactly.
// EPI: 0 = bias, 1 = bias+exact GELU, 2 = bias+residual (Res may alias Cc)
// ---------------------------------------------------------------------------
template<int EPI>
__global__ void sgemm_kernel(const float* __restrict__ A,
                             const float* __restrict__ Bm,
                             const float* __restrict__ bias,
                             const float* __restrict__ Res,
                             float* __restrict__ Cc,
                             int M, int Nn, int K) {
    __shared__ float As[8][128];
    __shared__ float Bs[8][128];
    int tid = threadIdx.x;
    int bx = blockIdx.x;   // N tile
    int by = blockIdx.y;   // M tile

    const float* Ab = A + (size_t)by * 128 * K;
    const float* Bb = Bm + (size_t)bx * 128;

    int arow = tid >> 1;           // 0..127
    int acol = (tid & 1) * 4;      // 0 or 4
    int brow = tid >> 5;           // 0..7
    int bcol = (tid & 31) * 4;     // 0..124

    int tx = tid & 15;             // 0..15
    int ty = tid >> 4;             // 0..15

    float acc[8][8];
    #pragma unroll
    for (int i = 0; i < 8; ++i)
        #pragma unroll
        for (int j = 0; j < 8; ++j) acc[i][j] = 0.f;

    for (int kt = 0; kt < K; kt += 8) {
        float4 av = *(const float4*)(Ab + (size_t)arow * K + kt + acol);
        As[acol + 0][arow] = av.x;
        As[acol + 1][arow] = av.y;
        As[acol + 2][arow] = av.z;
        As[acol + 3][arow] = av.w;
        *(float4*)&Bs[brow][bcol] =
            *(const float4*)(Bb + (size_t)(kt + brow) * Nn + bcol);
        __syncthreads();

        #pragma unroll
        for (int k = 0; k < 8; ++k) {
            float ar[8], br[8];
            *(float4*)(ar)     = *(const float4*)&As[k][ty * 8];
            *(float4*)(ar + 4) = *(const float4*)&As[k][ty * 8 + 4];
            *(float4*)(br)     = *(const float4*)&Bs[k][tx * 8];
            *(float4*)(br + 4) = *(const float4*)&Bs[k][tx * 8 + 4];
            #pragma unroll
            for (int i = 0; i < 8; ++i)
                #pragma unroll
                for (int j = 0; j < 8; ++j)
                    acc[i][j] = fmaf(ar[i], br[j], acc[i][j]);
        }
        __syncthreads();
    }

    #pragma unroll
    for (int i = 0; i < 8; ++i) {
        int row = by * 128 + ty * 8 + i;
        #pragma unroll
        for (int j = 0; j < 8; ++j) {
            int col = bx * 128 + tx * 8 + j;
            float v = acc[i][j] + bias[col];
            if (EPI == 1) {
                v = 0.5f * v * (1.f + erff(v * 0.70710678118654752f));
            } else if (EPI == 2) {
                v += Res[(size_t)row * Nn + col];
            }
            Cc[(size_t)row * Nn + col] = v;
        }
    }
}

// ---------------------------------------------------------------------------
// Multi-head self-attention for one (b,h): K,V in smem, 8 warps x queries.
// qkv layout per row: [q(0..767) k(768..1535) v(1536..2303)], head h at h*64.
// out layout: [b][n][h*64+d]  (== transpose(0,2,1,3).reshape)
// ---------------------------------------------------------------------------
#define KPAD 65
#define ATTN_SMEM ((196*KPAD*2 + 8*64 + 8*196) * (int)sizeof(float))

__global__ void attn_kernel(const float* __restrict__ qkv,
                            float* __restrict__ out) {
    extern __shared__ float sm[];
    float* Ks = sm;                       // [196][65]
    float* Vs = Ks + 196 * KPAD;          // [196][65]
    float* qs = Vs + 196 * KPAD;          // [8][64]
    float* ss = qs + 8 * 64;              // [8][196]

    int bh = blockIdx.x;
    int b = bh / H_, h = bh % H_;
    const float* base = qkv + (size_t)b * N_ * 3 * C_;

    for (int idx = threadIdx.x; idx < 196 * 64; idx += 256) {
        int j = idx >> 6, d = idx & 63;
        Ks[j * KPAD + d] = base[(size_t)j * (3 * C_) + C_ + h * HD_ + d];
        Vs[j * KPAD + d] = base[(size_t)j * (3 * C_) + 2 * C_ + h * HD_ + d];
    }
    __syncthreads();

    int warp = threadIdx.x >> 5, lane = threadIdx.x & 31;
    for (int q = warp; q < 196; q += 8) {
        qs[warp * 64 + lane]      = base[(size_t)q * (3 * C_) + h * HD_ + lane];
        qs[warp * 64 + 32 + lane] = base[(size_t)q * (3 * C_) + h * HD_ + 32 + lane];
        __syncwarp();

        float mymax = -1e30f;
        for (int j = lane; j < 196; j += 32) {
            float s = 0.f;
            #pragma unroll
            for (int d = 0; d < 64; ++d)
                s = fmaf(qs[warp * 64 + d], Ks[j * KPAD + d], s);
            s *= 0.125f;   // 1/sqrt(64)
            ss[warp * 196 + j] = s;
            mymax = fmaxf(mymax, s);
        }
        #pragma unroll
        for (int o = 16; o > 0; o >>= 1)
            mymax = fmaxf(mymax, __shfl_xor_sync(0xffffffffu, mymax, o));

        float mysum = 0.f;
        for (int j = lane; j < 196; j += 32) {
            float e = __expf(ss[warp * 196 + j] - mymax);
            ss[warp * 196 + j] = e;
            mysum += e;
        }
        #pragma unroll
        for (int o = 16; o > 0; o >>= 1)
            mysum += __shfl_xor_sync(0xffffffffu, mysum, o);
        float inv = 1.f / mysum;

        float o0 = 0.f, o1 = 0.f;
        for (int j = 0; j < 196; ++j) {
            float p = ss[warp * 196 + j];
            o0 = fmaf(p, Vs[j * KPAD + lane], o0);
            o1 = fmaf(p, Vs[j * KPAD + 32 + lane], o1);
        }
        out[(size_t)(b * N_ + q) * C_ + h * HD_ + lane]      = o0 * inv;
        out[(size_t)(b * N_ + q) * C_ + h * HD_ + 32 + lane] = o1 * inv;
        __syncwarp();
    }
}

// ---------------------------------------------------------------------------
// Latent bottleneck: fused[b,l,:] = softmax(lat[l] . concat / sqrt(C)) @ concat
// concat = [x[b] ; y[b]], 392 keys. One block per (b,l).
// ---------------------------------------------------------------------------
__global__ void latent_kernel(const float* __restrict__ x,
                              const float* __restrict__ y,
                              const float* __restrict__ lat,
                              float* __restrict__ fused) {
    __shared__ float lq[C_];
    __shared__ float sc[2 * N_];
    __shared__ float red[256];
    int b = blockIdx.x / L_, l = blockIdx.x % L_;
    int t = threadIdx.x;

    for (int i = t; i < C_; i += 256) lq[i] = lat[(size_t)l * C_ + i];
    __syncthreads();

    float mymax = -1e30f;
    for (int j = t; j < 2 * N_; j += 256) {
        const float* kr = (j < N_) ? (x + ((size_t)b * N_ + j) * C_)
                                   : (y + ((size_t)b * N_ + (j - N_)) * C_);
        float s = 0.f;
        for (int d = 0; d < C_; ++d) s = fmaf(lq[d], kr[d], s);
        s *= 0.03608439182435161f;   // 1/sqrt(768)
        sc[j] = s;
        mymax = fmaxf(mymax, s);
    }
    red[t] = mymax;
    __syncthreads();
    for (int o = 128; o > 0; o >>= 1) {
        if (t < o) red[t] = fmaxf(red[t], red[t + o]);
        __syncthreads();
    }
    float gmax = red[0];
    __syncthreads();

    float mysum = 0.f;
    for (int j = t; j < 2 * N_; j += 256) {
        float e = __expf(sc[j] - gmax);
        sc[j] = e;
        mysum += e;
    }
    red[t] = mysum;
    __syncthreads();
    for (int o = 128; o > 0; o >>= 1) {
        if (t < o) red[t] += red[t + o];
        __syncthreads();
    }
    float inv = 1.f / red[0];
    __syncthreads();

    for (int c = t; c < C_; c += 256) {
        float acc = 0.f;
        for (int j = 0; j < N_; ++j)
            acc = fmaf(sc[j], x[((size_t)b * N_ + j) * C_ + c], acc);
        for (int j = 0; j < N_; ++j)
            acc = fmaf(sc[N_ + j], y[((size_t)b * N_ + j) * C_ + c], acc);
        fused[((size_t)b * L_ + l) * C_ + c] = acc * inv;
    }
}

// ---------------------------------------------------------------------------
// Cross-attn against 4 latent rows: out = in + scale * sdpa(in, fused, fused)
// Block handles 8 queries (1/warp). fused[b] (4x768) cached in smem.
// ---------------------------------------------------------------------------
__global__ void cross_kernel(const float* __restrict__ xin,
                             const float* __restrict__ fused,
                             const float* __restrict__ scale,
                             float* __restrict__ xout) {
    __shared__ float fs[L_ * C_];
    int b = blockIdx.x / 25, tile = blockIdx.x % 25;
    int t = threadIdx.x;
    for (int i = t; i < L_ * C_; i += 256)
        fs[i] = fused[(size_t)b * L_ * C_ + i];
    __syncthreads();

    int warp = t >> 5, lane = t & 31;
    int q = tile * 8 + warp;
    if (q >= N_) return;

    const float* qr = xin + ((size_t)b * N_ + q) * C_;
    float s0 = 0.f, s1 = 0.f, s2 = 0.f, s3 = 0.f;
    for (int d = lane; d < C_; d += 32) {
        float qa = qr[d];
        s0 = fmaf(qa, fs[d], s0);
        s1 = fmaf(qa, fs[C_ + d], s1);
        s2 = fmaf(qa, fs[2 * C_ + d], s2);
        s3 = fmaf(qa, fs[3 * C_ + d], s3);
    }
    #pragma unroll
    for (int o = 16; o > 0; o >>= 1) {
        s0 += __shfl_xor_sync(0xffffffffu, s0, o);
        s1 += __shfl_xor_sync(0xffffffffu, s1, o);
        s2 += __shfl_xor_sync(0xffffffffu, s2, o);
        s3 += __shfl_xor_sync(0xffffffffu, s3, o);
    }
    const float sfac = 0.03608439182435161f;  // 1/sqrt(768)
    s0 *= sfac; s1 *= sfac; s2 *= sfac; s3 *= sfac;
    float m = fmaxf(fmaxf(s0, s1), fmaxf(s2, s3));
    float p0 = __expf(s0 - m), p1 = __expf(s1 - m);
    float p2 = __expf(s2 - m), p3 = __expf(s3 - m);
    float inv = 1.f / (p0 + p1 + p2 + p3);
    float sc = scale[0] * inv;

    float* orow = xout + ((size_t)b * N_ + q) * C_;
    for (int d = lane; d < C_; d += 32) {
        float o = p0 * fs[d] + p1 * fs[C_ + d] + p2 * fs[2 * C_ + d] + p3 * fs[3 * C_ + d];
        orow[d] = qr[d] + sc * o;
    }
}

// ---------------------------------------------------------------------------
// Host launch
// ---------------------------------------------------------------------------
extern "C" void kernel_launch(void* const* d_in, const int* in_sizes, int n_in,
                              void* d_out, int out_size) {
    const float* x        = (const float*)d_in[0];
    const float* y        = (const float*)d_in[1];
    const float* latents  = (const float*)d_in[2];
    const float* scale_a  = (const float*)d_in[3];
    const float* scale_v  = (const float*)d_in[4];

    // per-stream params: [ln1_g, ln1_b, qkv_w, qkv_b, proj_w, proj_b,
    //                     ln2_g, ln2_b, fc1_w, fc1_b, fc2_w, fc2_b]
    const float* sp[12];
    const float* rp[12];
    for (int i = 0; i < 12; ++i) {
        sp[i] = (const float*)d_in[5 + i];
        rp[i] = (const float*)d_in[17 + i];
    }

    float* outx = (float*)d_out;
    float* outy = outx + (size_t)ROWS_ * C_;

    float *p_ln, *p_qkv, *p_attn, *p_hid, *p_fused;
    cudaGetSymbolAddress((void**)&p_ln, g_ln);
    cudaGetSymbolAddress((void**)&p_qkv, g_qkv);
    cudaGetSymbolAddress((void**)&p_attn, g_attn);
    cudaGetSymbolAddress((void**)&p_hid, g_hidden);
    cudaGetSymbolAddress((void**)&p_fused, g_fused);

    cudaFuncSetAttribute(attn_kernel,
                         cudaFuncAttributeMaxDynamicSharedMemorySize, ATTN_SMEM);

    // --- latent bottleneck fusion ---
    latent_kernel<<<B_ * L_, 256>>>(x, y, latents, p_fused);
    cross_kernel<<<B_ * 25, 256>>>(x, p_fused, scale_a, outx);
    cross_kernel<<<B_ * 25, 256>>>(y, p_fused, scale_v, outy);

    // --- per-stream ViT block ---
    for (int s = 0; s < 2; ++s) {
        const float** P = (s == 0) ? sp : rp;
        float* xb = (s == 0) ? outx : outy;

        ln_kernel<<<ROWS_, 256>>>(xb, P[0], P[1], p_ln);
        sgemm_kernel<0><<<dim3(3 * C_ / 128, ROWS_ / 128), 256>>>(
            p_ln, P[2], P[3], nullptr, p_qkv, ROWS_, 3 * C_, C_);
        attn_kernel<<<B_ * H_, 256, ATTN_SMEM>>>(p_qkv, p_attn);
        sgemm_kernel<2><<<dim3(C_ / 128, ROWS_ / 128), 256>>>(
            p_attn, P[4], P[5], xb, xb, ROWS_, C_, C_);
        ln_kernel<<<ROWS_, 256>>>(xb, P[6], P[7], p_ln);
        sgemm_kernel<1><<<dim3(DFF_ / 128, ROWS_ / 128), 256>>>(
            p_ln, P[8], P[9], nullptr, p_hid, ROWS_, DFF_, C_);
        sgemm_kernel<2><<<dim3(C_ / 128, ROWS_ / 128), 256>>>(
            p_hid, P[10], P[11], xb, xb, ROWS_, C_, DFF_);
    }
}

// round 2
// speedup vs baseline: 2.0065x; 2.0065x over previous
#include <cuda_runtime.h>
#include <math.h>
#include <stdint.h>

// Problem constants
#define B_ 32
#define N_ 196
#define C_ 768
#define H_ 12
#define L_ 4
#define DFF_ 3072
#define ROWS_ (B_*N_)          // 6272
#define HD_ 64                 // C_/H_

// ---------------- scratch (device globals; no runtime allocation) ----------
__device__ float g_ln[ROWS_*C_];          // LN output
__device__ float g_qkv[ROWS_*3*C_];       // qkv projection
__device__ float g_attn[ROWS_*C_];        // attention output (head-concat)
__device__ float g_hidden[ROWS_*DFF_];    // MLP hidden
__device__ float g_fused[B_*L_*C_];       // latent bottleneck output

// ---------------------------------------------------------------------------
// LayerNorm: one block (256 thr) per row, C=768 => 3 elems/thread
// ---------------------------------------------------------------------------
__global__ void ln_kernel(const float* __restrict__ in,
                          const float* __restrict__ gam,
                          const float* __restrict__ bet,
                          float* __restrict__ out) {
    __shared__ float red[256];
    int row = blockIdx.x, t = threadIdx.x;
    const float* r = in + (size_t)row * C_;
    float v0 = r[t], v1 = r[t + 256], v2 = r[t + 512];
    red[t] = v0 + v1 + v2;
    __syncthreads();
    #pragma unroll
    for (int o = 128; o > 0; o >>= 1) {
        if (t < o) red[t] += red[t + o];
        __syncthreads();
    }
    float mean = red[0] * (1.f / C_);
    __syncthreads();
    float d0 = v0 - mean, d1 = v1 - mean, d2 = v2 - mean;
    red[t] = d0 * d0 + d1 * d1 + d2 * d2;
    __syncthreads();
    #pragma unroll
    for (int o = 128; o > 0; o >>= 1) {
        if (t < o) red[t] += red[t + o];
        __syncthreads();
    }
    float inv = rsqrtf(red[0] * (1.f / C_) + 1e-6f);
    float* o = out + (size_t)row * C_;
    o[t]       = d0 * inv * gam[t]       + bet[t];
    o[t + 256] = d1 * inv * gam[t + 256] + bet[t + 256];
    o[t + 512] = d2 * inv * gam[t + 512] + bet[t + 512];
}

// ---------------------------------------------------------------------------
// TF32 tensor-core GEMM: C[M,N] = A[M,K] @ B[K,N] (+bias)(+gelu|+residual)
// BM=BN=128, BK=16, 256 threads (8 warps, 2x4), warp tile 64x32 via
// mma.sync.m16n8k8.tf32 (4x4 mma tiles). cp.async double-buffered.
// EPI: 0 = bias, 1 = bias+exact GELU, 2 = bias+residual (Res may alias Cc)
// ---------------------------------------------------------------------------
#define CPA16(dst, src) \
    asm volatile("cp.async.cg.shared.global [%0], [%1], 16;\n" :: \
        "r"((unsigned)__cvta_generic_to_shared(dst)), "l"(src))

__device__ __forceinline__ uint32_t f2tf32(float f) {
    uint32_t u;
    asm volatile("cvt.rna.tf32.f32 %0, %1;\n" : "=r"(u) : "f"(f));
    return u;
}

template<int EPI>
__global__ void __launch_bounds__(256, 2)
tgemm_kernel(const float* __restrict__ A,
             const float* __restrict__ Bm,
             const float* __restrict__ bias,
             const float* __restrict__ Res,
             float* __restrict__ Cc,
             int M, int Nn, int K) {
    // A tile stored [row][k]: row stride 20 floats (80B: 16B-aligned rows,
    // conflict-free fragment reads). B tile [k][n]: row stride 132 floats.
    __shared__ float As[2][128][20];
    __shared__ float Bs[2][16][132];

    int tid = threadIdx.x;
    int warp = tid >> 5, lane = tid & 31;
    int g = lane >> 2, t = lane & 3;          // groupID, threadID_in_group
    int wm = (warp >> 2) * 64;                // warp M offset in tile
    int wn = (warp & 3) * 32;                 // warp N offset in tile
    int bx = blockIdx.x, by = blockIdx.y;

    const float* Ab = A + (size_t)by * 128 * K;
    const float* Bb = Bm + (size_t)bx * 128;

    int ar = tid >> 1, ac = (tid & 1) * 4;    // A loader: 2 float4/thread
    int br = tid >> 4, bc = (tid & 15) * 4;   // B loader: 2 float4/thread

    float acc[4][4][4];
    #pragma unroll
    for (int i = 0; i < 4; ++i)
        #pragma unroll
        for (int j = 0; j < 4; ++j)
            #pragma unroll
            for (int r = 0; r < 4; ++r) acc[i][j][r] = 0.f;

    // prologue: load tile 0 into buf 0
    {
        CPA16(&As[0][ar][ac],     Ab + (size_t)ar * K + ac);
        CPA16(&As[0][ar][ac + 8], Ab + (size_t)ar * K + ac + 8);
        CPA16(&Bs[0][br][bc],      Bb + (size_t)br * Nn + bc);
        CPA16(&Bs[0][br][bc + 64], Bb + (size_t)br * Nn + bc + 64);
        asm volatile("cp.async.commit_group;\n");
    }

    int nk = K >> 4;
    for (int kt = 0; kt < nk; ++kt) {
        int buf = kt & 1;
        if (kt + 1 < nk) {
            int kk = (kt + 1) << 4;
            int nb = buf ^ 1;
            CPA16(&As[nb][ar][ac],     Ab + (size_t)ar * K + kk + ac);
            CPA16(&As[nb][ar][ac + 8], Ab + (size_t)ar * K + kk + ac + 8);
            CPA16(&Bs[nb][br][bc],      Bb + (size_t)(kk + br) * Nn + bc);
            CPA16(&Bs[nb][br][bc + 64], Bb + (size_t)(kk + br) * Nn + bc + 64);
            asm volatile("cp.async.commit_group;\n");
            asm volatile("cp.async.wait_group 1;\n");
        } else {
            asm volatile("cp.async.wait_group 0;\n");
        }
        __syncthreads();

        #pragma unroll
        for (int k8 = 0; k8 < 16; k8 += 8) {
            uint32_t af[4][4], bf[4][2];
            #pragma unroll
            for (int i = 0; i < 4; ++i) {
                af[i][0] = f2tf32(As[buf][wm + 16 * i + g    ][k8 + t]);
                af[i][1] = f2tf32(As[buf][wm + 16 * i + g + 8][k8 + t]);
                af[i][2] = f2tf32(As[buf][wm + 16 * i + g    ][k8 + t + 4]);
                af[i][3] = f2tf32(As[buf][wm + 16 * i + g + 8][k8 + t + 4]);
            }
            #pragma unroll
            for (int j = 0; j < 4; ++j) {
                bf[j][0] = f2tf32(Bs[buf][k8 + t    ][wn + 8 * j + g]);
                bf[j][1] = f2tf32(Bs[buf][k8 + t + 4][wn + 8 * j + g]);
            }
            #pragma unroll
            for (int i = 0; i < 4; ++i)
                #pragma unroll
                for (int j = 0; j < 4; ++j) {
                    asm volatile(
                        "mma.sync.aligned.m16n8k8.row.col.f32.tf32.tf32.f32 "
                        "{%0,%1,%2,%3}, {%4,%5,%6,%7}, {%8,%9}, {%0,%1,%2,%3};\n"
                        : "+f"(acc[i][j][0]), "+f"(acc[i][j][1]),
                          "+f"(acc[i][j][2]), "+f"(acc[i][j][3])
                        : "r"(af[i][0]), "r"(af[i][1]), "r"(af[i][2]), "r"(af[i][3]),
                          "r"(bf[j][0]), "r"(bf[j][1]));
                }
        }
        __syncthreads();
    }

    // epilogue: c0:(g,2t) c1:(g,2t+1) c2:(g+8,2t) c3:(g+8,2t+1)
    #pragma unroll
    for (int i = 0; i < 4; ++i) {
        int row0 = by * 128 + wm + 16 * i + g;
        #pragma unroll
        for (int j = 0; j < 4; ++j) {
            int col = bx * 128 + wn + 8 * j + 2 * t;
            float bb0 = bias[col], bb1 = bias[col + 1];
            float v00 = acc[i][j][0] + bb0;
            float v01 = acc[i][j][1] + bb1;
            float v10 = acc[i][j][2] + bb0;
            float v11 = acc[i][j][3] + bb1;
            if (EPI == 1) {
                v00 = 0.5f * v00 * (1.f + erff(v00 * 0.70710678118654752f));
                v01 = 0.5f * v01 * (1.f + erff(v01 * 0.70710678118654752f));
                v10 = 0.5f * v10 * (1.f + erff(v10 * 0.70710678118654752f));
                v11 = 0.5f * v11 * (1.f + erff(v11 * 0.70710678118654752f));
            } else if (EPI == 2) {
                float2 r0 = *(const float2*)(Res + (size_t)row0 * Nn + col);
                float2 r1 = *(const float2*)(Res + (size_t)(row0 + 8) * Nn + col);
                v00 += r0.x; v01 += r0.y;
                v10 += r1.x; v11 += r1.y;
            }
            *(float2*)(Cc + (size_t)row0 * Nn + col) = make_float2(v00, v01);
            *(float2*)(Cc + (size_t)(row0 + 8) * Nn + col) = make_float2(v10, v11);
        }
    }
}

// ---------------------------------------------------------------------------
// Multi-head self-attention for one (b,h): K,V in smem, 8 warps x queries.
// ---------------------------------------------------------------------------
#define KPAD 65
#define ATTN_SMEM ((196*KPAD*2 + 8*64 + 8*196) * (int)sizeof(float))

__global__ void attn_kernel(const float* __restrict__ qkv,
                            float* __restrict__ out) {
    extern __shared__ float sm[];
    float* Ks = sm;                       // [196][65]
    float* Vs = Ks + 196 * KPAD;          // [196][65]
    float* qs = Vs + 196 * KPAD;          // [8][64]
    float* ss = qs + 8 * 64;              // [8][196]

    int bh = blockIdx.x;
    int b = bh / H_, h = bh % H_;
    const float* base = qkv + (size_t)b * N_ * 3 * C_;

    for (int idx = threadIdx.x; idx < 196 * 64; idx += 256) {
        int j = idx >> 6, d = idx & 63;
        Ks[j * KPAD + d] = base[(size_t)j * (3 * C_) + C_ + h * HD_ + d];
        Vs[j * KPAD + d] = base[(size_t)j * (3 * C_) + 2 * C_ + h * HD_ + d];
    }
    __syncthreads();

    int warp = threadIdx.x >> 5, lane = threadIdx.x & 31;
    for (int q = warp; q < 196; q += 8) {
        qs[warp * 64 + lane]      = base[(size_t)q * (3 * C_) + h * HD_ + lane];
        qs[warp * 64 + 32 + lane] = base[(size_t)q * (3 * C_) + h * HD_ + 32 + lane];
        __syncwarp();

        float mymax = -1e30f;
        for (int j = lane; j < 196; j += 32) {
            float s = 0.f;
            #pragma unroll
            for (int d = 0; d < 64; ++d)
                s = fmaf(qs[warp * 64 + d], Ks[j * KPAD + d], s);
            s *= 0.125f;   // 1/sqrt(64)
            ss[warp * 196 + j] = s;
            mymax = fmaxf(mymax, s);
        }
        #pragma unroll
        for (int o = 16; o > 0; o >>= 1)
            mymax = fmaxf(mymax, __shfl_xor_sync(0xffffffffu, mymax, o));

        float mysum = 0.f;
        for (int j = lane; j < 196; j += 32) {
            float e = __expf(ss[warp * 196 + j] - mymax);
            ss[warp * 196 + j] = e;
            mysum += e;
        }
        #pragma unroll
        for (int o = 16; o > 0; o >>= 1)
            mysum += __shfl_xor_sync(0xffffffffu, mysum, o);
        float inv = 1.f / mysum;

        float o0 = 0.f, o1 = 0.f;
        for (int j = 0; j < 196; ++j) {
            float p = ss[warp * 196 + j];
            o0 = fmaf(p, Vs[j * KPAD + lane], o0);
            o1 = fmaf(p, Vs[j * KPAD + 32 + lane], o1);
        }
        out[(size_t)(b * N_ + q) * C_ + h * HD_ + lane]      = o0 * inv;
        out[(size_t)(b * N_ + q) * C_ + h * HD_ + 32 + lane] = o1 * inv;
        __syncwarp();
    }
}

// ---------------------------------------------------------------------------
// Latent bottleneck: fused[b,l,:] = softmax(lat[l] . concat / sqrt(C)) @ concat
// ---------------------------------------------------------------------------
__global__ void latent_kernel(const float* __restrict__ x,
                              const float* __restrict__ y,
                              const float* __restrict__ lat,
                              float* __restrict__ fused) {
    __shared__ float lq[C_];
    __shared__ float sc[2 * N_];
    __shared__ float red[256];
    int b = blockIdx.x / L_, l = blockIdx.x % L_;
    int t = threadIdx.x;

    for (int i = t; i < C_; i += 256) lq[i] = lat[(size_t)l * C_ + i];
    __syncthreads();

    float mymax = -1e30f;
    for (int j = t; j < 2 * N_; j += 256) {
        const float* kr = (j < N_) ? (x + ((size_t)b * N_ + j) * C_)
                                   : (y + ((size_t)b * N_ + (j - N_)) * C_);
        float s = 0.f;
        for (int d = 0; d < C_; ++d) s = fmaf(lq[d], kr[d], s);
        s *= 0.03608439182435161f;   // 1/sqrt(768)
        sc[j] = s;
        mymax = fmaxf(mymax, s);
    }
    red[t] = mymax;
    __syncthreads();
    for (int o = 128; o > 0; o >>= 1) {
        if (t < o) red[t] = fmaxf(red[t], red[t + o]);
        __syncthreads();
    }
    float gmax = red[0];
    __syncthreads();

    float mysum = 0.f;
    for (int j = t; j < 2 * N_; j += 256) {
        float e = __expf(sc[j] - gmax);
        sc[j] = e;
        mysum += e;
    }
    red[t] = mysum;
    __syncthreads();
    for (int o = 128; o > 0; o >>= 1) {
        if (t < o) red[t] += red[t + o];
        __syncthreads();
    }
    float inv = 1.f / red[0];
    __syncthreads();

    for (int c = t; c < C_; c += 256) {
        float acc = 0.f;
        for (int j = 0; j < N_; ++j)
            acc = fmaf(sc[j], x[((size_t)b * N_ + j) * C_ + c], acc);
        for (int j = 0; j < N_; ++j)
            acc = fmaf(sc[N_ + j], y[((size_t)b * N_ + j) * C_ + c], acc);
        fused[((size_t)b * L_ + l) * C_ + c] = acc * inv;
    }
}

// ---------------------------------------------------------------------------
// Cross-attn against 4 latent rows: out = in + scale * sdpa(in, fused, fused)
// ---------------------------------------------------------------------------
__global__ void cross_kernel(const float* __restrict__ xin,
                             const float* __restrict__ fused,
                             const float* __restrict__ scale,
                             float* __restrict__ xout) {
    __shared__ float fs[L_ * C_];
    int b = blockIdx.x / 25, tile = blockIdx.x % 25;
    int t = threadIdx.x;
    for (int i = t; i < L_ * C_; i += 256)
        fs[i] = fused[(size_t)b * L_ * C_ + i];
    __syncthreads();

    int warp = t >> 5, lane = t & 31;
    int q = tile * 8 + warp;
    if (q >= N_) return;

    const float* qr = xin + ((size_t)b * N_ + q) * C_;
    float s0 = 0.f, s1 = 0.f, s2 = 0.f, s3 = 0.f;
    for (int d = lane; d < C_; d += 32) {
        float qa = qr[d];
        s0 = fmaf(qa, fs[d], s0);
        s1 = fmaf(qa, fs[C_ + d], s1);
        s2 = fmaf(qa, fs[2 * C_ + d], s2);
        s3 = fmaf(qa, fs[3 * C_ + d], s3);
    }
    #pragma unroll
    for (int o = 16; o > 0; o >>= 1) {
        s0 += __shfl_xor_sync(0xffffffffu, s0, o);
        s1 += __shfl_xor_sync(0xffffffffu, s1, o);
        s2 += __shfl_xor_sync(0xffffffffu, s2, o);
        s3 += __shfl_xor_sync(0xffffffffu, s3, o);
    }
    const float sfac = 0.03608439182435161f;  // 1/sqrt(768)
    s0 *= sfac; s1 *= sfac; s2 *= sfac; s3 *= sfac;
    float m = fmaxf(fmaxf(s0, s1), fmaxf(s2, s3));
    float p0 = __expf(s0 - m), p1 = __expf(s1 - m);
    float p2 = __expf(s2 - m), p3 = __expf(s3 - m);
    float inv = 1.f / (p0 + p1 + p2 + p3);
    float sc = scale[0] * inv;

    float* orow = xout + ((size_t)b * N_ + q) * C_;
    for (int d = lane; d < C_; d += 32) {
        float o = p0 * fs[d] + p1 * fs[C_ + d] + p2 * fs[2 * C_ + d] + p3 * fs[3 * C_ + d];
        orow[d] = qr[d] + sc * o;
    }
}

// ---------------------------------------------------------------------------
// Host launch
// ---------------------------------------------------------------------------
extern "C" void kernel_launch(void* const* d_in, const int* in_sizes, int n_in,
                              void* d_out, int out_size) {
    const float* x        = (const float*)d_in[0];
    const float* y        = (const float*)d_in[1];
    const float* latents  = (const float*)d_in[2];
    const float* scale_a  = (const float*)d_in[3];
    const float* scale_v  = (const float*)d_in[4];

    const float* sp[12];
    const float* rp[12];
    for (int i = 0; i < 12; ++i) {
        sp[i] = (const float*)d_in[5 + i];
        rp[i] = (const float*)d_in[17 + i];
    }

    float* outx = (float*)d_out;
    float* outy = outx + (size_t)ROWS_ * C_;

    float *p_ln, *p_qkv, *p_attn, *p_hid, *p_fused;
    cudaGetSymbolAddress((void**)&p_ln, g_ln);
    cudaGetSymbolAddress((void**)&p_qkv, g_qkv);
    cudaGetSymbolAddress((void**)&p_attn, g_attn);
    cudaGetSymbolAddress((void**)&p_hid, g_hidden);
    cudaGetSymbolAddress((void**)&p_fused, g_fused);

    cudaFuncSetAttribute(attn_kernel,
                         cudaFuncAttributeMaxDynamicSharedMemorySize, ATTN_SMEM);

    // --- latent bottleneck fusion ---
    latent_kernel<<<B_ * L_, 256>>>(x, y, latents, p_fused);
    cross_kernel<<<B_ * 25, 256>>>(x, p_fused, scale_a, outx);
    cross_kernel<<<B_ * 25, 256>>>(y, p_fused, scale_v, outy);

    // --- per-stream ViT block ---
    for (int s = 0; s < 2; ++s) {
        const float** P = (s == 0) ? sp : rp;
        float* xb = (s == 0) ? outx : outy;

        ln_kernel<<<ROWS_, 256>>>(xb, P[0], P[1], p_ln);
        tgemm_kernel<0><<<dim3(3 * C_ / 128, ROWS_ / 128), 256>>>(
            p_ln, P[2], P[3], nullptr, p_qkv, ROWS_, 3 * C_, C_);
        attn_kernel<<<B_ * H_, 256, ATTN_SMEM>>>(p_qkv, p_attn);
        tgemm_kernel<2><<<dim3(C_ / 128, ROWS_ / 128), 256>>>(
            p_attn, P[4], P[5], xb, xb, ROWS_, C_, C_);
        ln_kernel<<<ROWS_, 256>>>(xb, P[6], P[7], p_ln);
        tgemm_kernel<1><<<dim3(DFF_ / 128, ROWS_ / 128), 256>>>(
            p_ln, P[8], P[9], nullptr, p_hid, ROWS_, DFF_, C_);
        tgemm_kernel<2><<<dim3(C_ / 128, ROWS_ / 128), 256>>>(
            p_hid, P[10], P[11], xb, xb, ROWS_, C_, DFF_);
    }
}